// round 1
// baseline (speedup 1.0000x reference)
#include <cuda_runtime.h>

// Problem constants
constexpr int B_  = 4;
constexpr int G_  = 8;
constexpr int NH_ = 8;
constexpr int DIM_ = 256;   // HID / G
constexpr int S_   = 4096;
constexpr int SP_  = 4097;  // padded time dim (extra zero column)
constexpr int HID_ = 2048;

// Scratch (device globals; allocation is forbidden)
__device__ float g_Q[(size_t)B_ * G_ * DIM_ * S_];   // (b,g,c,s)
__device__ float g_K[(size_t)B_ * G_ * DIM_ * SP_];  // (b,g,c,t) t in [0,4096]
__device__ float g_V[(size_t)B_ * G_ * DIM_ * SP_];
__device__ float g_O[(size_t)B_ * G_ * DIM_ * S_];   // attention output

// ---------------------------------------------------------------------------
// Kernel 1: per-(b,g) GEMM  Y(768 x 4097) = W(768x256) @ X(256x4097)
// X = x[b, g*256 : (g+1)*256, :] padded with a zero column at t=4096.
// Row o maps to (c2 = o/3, j = o%3) -> Q/K/V scatter.
// ---------------------------------------------------------------------------
__global__ __launch_bounds__(256)
void qkv_gemm(const float* __restrict__ x, const float* __restrict__ w,
              const float* __restrict__ bias) {
    __shared__ float As[16][128];  // [k][o]
    __shared__ float Bs[16][128];  // [k][t]
    const int bg = blockIdx.z;
    const int b  = bg >> 3;
    const int g  = bg & 7;
    const int o0 = blockIdx.y << 7;       // 0..640
    const int t0 = blockIdx.x << 7;       // 0..4096 (33 tiles)
    const float* W = w + (size_t)g * 768 * 256;
    const float* X = x + (size_t)(b * HID_ + g * DIM_) * S_;
    const int tid = threadIdx.x;
    const int tr  = tid >> 4;   // 0..15
    const int tc  = tid & 15;   // 0..15

    float acc[8][8];
#pragma unroll
    for (int i = 0; i < 8; i++) {
#pragma unroll
        for (int j = 0; j < 8; j++) acc[i][j] = 0.f;
    }
    const bool inb = (t0 < S_);  // tile 32 reads all zeros (pad column)

    for (int k0 = 0; k0 < 256; k0 += 16) {
        // W tile: 128 rows(o) x 16 cols(c) -> As[c][o]
#pragma unroll
        for (int l = 0; l < 2; l++) {
            int f   = tid + (l << 8);       // float4 id 0..511
            int row = f >> 2;               // 0..127
            int cq  = (f & 3) << 2;         // 0,4,8,12
            float4 wv = *reinterpret_cast<const float4*>(
                W + (size_t)(o0 + row) * 256 + k0 + cq);
            As[cq + 0][row] = wv.x;
            As[cq + 1][row] = wv.y;
            As[cq + 2][row] = wv.z;
            As[cq + 3][row] = wv.w;
        }
        // X tile: 16 rows(c) x 128 cols(t)
#pragma unroll
        for (int l = 0; l < 2; l++) {
            int f   = tid + (l << 8);
            int row = f >> 5;               // 0..15
            int col = (f & 31) << 2;        // 0..124
            float4 xv = make_float4(0.f, 0.f, 0.f, 0.f);
            if (inb)
                xv = *reinterpret_cast<const float4*>(
                    X + (size_t)(k0 + row) * S_ + t0 + col);
            *reinterpret_cast<float4*>(&Bs[row][col]) = xv;
        }
        __syncthreads();
#pragma unroll
        for (int kk = 0; kk < 16; kk++) {
            float a[8], bb[8];
#pragma unroll
            for (int i = 0; i < 8; i += 4)
                *reinterpret_cast<float4*>(&a[i]) =
                    *reinterpret_cast<const float4*>(&As[kk][tr * 8 + i]);
#pragma unroll
            for (int j = 0; j < 8; j += 4)
                *reinterpret_cast<float4*>(&bb[j]) =
                    *reinterpret_cast<const float4*>(&Bs[kk][tc * 8 + j]);
#pragma unroll
            for (int i = 0; i < 8; i++) {
#pragma unroll
                for (int j = 0; j < 8; j++) acc[i][j] += a[i] * bb[j];
            }
        }
        __syncthreads();
    }
    // Epilogue: scatter to Q/K/V
#pragma unroll
    for (int i = 0; i < 8; i++) {
        int o  = o0 + tr * 8 + i;
        int c2 = o / 3;
        int jj = o - c2 * 3;
        float bv = bias[g * 768 + o];
        float* dst;
        int lim;
        if (jj == 0)      { dst = g_Q + (size_t)(bg * DIM_ + c2) * S_;  lim = S_; }
        else if (jj == 1) { dst = g_K + (size_t)(bg * DIM_ + c2) * SP_; lim = SP_; }
        else              { dst = g_V + (size_t)(bg * DIM_ + c2) * SP_; lim = SP_; }
#pragma unroll
        for (int j = 0; j < 8; j++) {
            int t = t0 + tc * 8 + j;
            if (t < lim) dst[t] = acc[i][j] + bv;
        }
    }
}

// ---------------------------------------------------------------------------
// Kernel 2: attention. One thread per (b, n, s). s is the lane dim -> all
// global accesses coalesced. scores[8][16] in registers; no shuffles.
// ---------------------------------------------------------------------------
__global__ __launch_bounds__(128)
void attn_kernel(float* __restrict__ attn_out) {
    const int s = blockIdx.x * 128 + threadIdx.x;
    const int n = blockIdx.y;
    const int b = blockIdx.z;

    float sc[8][16];
#pragma unroll
    for (int g = 0; g < 8; g++) {
#pragma unroll
        for (int e = 0; e < 16; e++) sc[g][e] = 0.f;
    }
    const size_t qbase = ((size_t)b * G_ * DIM_ + n * 32) * S_ + s;
    const size_t kbase = ((size_t)b * G_ * DIM_ + n * 32) * SP_ + s;

#pragma unroll 4
    for (int d = 0; d < 32; d++) {
        float qv[8], kv[16];
#pragma unroll
        for (int g = 0; g < 8; g++)
            qv[g] = g_Q[qbase + (size_t)(g * DIM_ + d) * S_];
#pragma unroll
        for (int e = 0; e < 8; e++) {
            size_t ko = kbase + (size_t)(e * DIM_ + d) * SP_;
            kv[e]     = g_K[ko];
            kv[e + 8] = g_K[ko + 1];  // time-shifted keys
        }
#pragma unroll
        for (int g = 0; g < 8; g++) {
#pragma unroll
            for (int e = 0; e < 16; e++) sc[g][e] += qv[g] * kv[e];
        }
    }

    const float scale = 0.17677669529663687f;  // 1/sqrt(32)
    const size_t abase = (size_t)(b * NH_ + n) * 128 * S_ + s;  // + (g*16+e)*S
#pragma unroll
    for (int g = 0; g < 8; g++) {
        float rs = 1e-9f;
#pragma unroll
        for (int e = 0; e < 16; e++) {
            float z = 1.f / (1.f + __expf(-sc[g][e] * scale));
            sc[g][e] = z;
            rs += z;
        }
        float inv = 1.f / rs;
#pragma unroll
        for (int e = 0; e < 16; e++) {
            sc[g][e] *= inv;
            attn_out[abase + (size_t)(g * 16 + e) * S_] = sc[g][e];
        }
    }

#pragma unroll 2
    for (int d = 0; d < 32; d++) {
        float vv[16];
#pragma unroll
        for (int e = 0; e < 8; e++) {
            size_t vo = kbase + (size_t)(e * DIM_ + d) * SP_;
            vv[e]     = g_V[vo];
            vv[e + 8] = g_V[vo + 1];
        }
#pragma unroll
        for (int g = 0; g < 8; g++) {
            float a = 0.f;
#pragma unroll
            for (int e = 0; e < 16; e++) a += sc[g][e] * vv[e];
            g_O[qbase + (size_t)(g * DIM_ + d) * S_] = a;
        }
    }
}

// ---------------------------------------------------------------------------
// Kernel 3: per-(b,g) GEMM  pred(256 x 4096) = Wp(256x256) @ O(256x4096)
// ---------------------------------------------------------------------------
__global__ __launch_bounds__(256)
void pred_gemm(const float* __restrict__ w, const float* __restrict__ bias,
               float* __restrict__ pred) {
    __shared__ float As[16][128];
    __shared__ float Bs[16][128];
    const int bg = blockIdx.z;
    const int g  = bg & 7;
    const int o0 = blockIdx.y << 7;  // 0,128
    const int t0 = blockIdx.x << 7;  // exact 32 tiles
    const float* W = w + (size_t)g * 256 * 256;
    const float* X = g_O + (size_t)bg * DIM_ * S_;
    const int tid = threadIdx.x;
    const int tr  = tid >> 4;
    const int tc  = tid & 15;

    float acc[8][8];
#pragma unroll
    for (int i = 0; i < 8; i++) {
#pragma unroll
        for (int j = 0; j < 8; j++) acc[i][j] = 0.f;
    }

    for (int k0 = 0; k0 < 256; k0 += 16) {
#pragma unroll
        for (int l = 0; l < 2; l++) {
            int f   = tid + (l << 8);
            int row = f >> 2;
            int cq  = (f & 3) << 2;
            float4 wv = *reinterpret_cast<const float4*>(
                W + (size_t)(o0 + row) * 256 + k0 + cq);
            As[cq + 0][row] = wv.x;
            As[cq + 1][row] = wv.y;
            As[cq + 2][row] = wv.z;
            As[cq + 3][row] = wv.w;
        }
#pragma unroll
        for (int l = 0; l < 2; l++) {
            int f   = tid + (l << 8);
            int row = f >> 5;
            int col = (f & 31) << 2;
            *reinterpret_cast<float4*>(&Bs[row][col]) =
                *reinterpret_cast<const float4*>(
                    X + (size_t)(k0 + row) * S_ + t0 + col);
        }
        __syncthreads();
#pragma unroll
        for (int kk = 0; kk < 16; kk++) {
            float a[8], bb[8];
#pragma unroll
            for (int i = 0; i < 8; i += 4)
                *reinterpret_cast<float4*>(&a[i]) =
                    *reinterpret_cast<const float4*>(&As[kk][tr * 8 + i]);
#pragma unroll
            for (int j = 0; j < 8; j += 4)
                *reinterpret_cast<float4*>(&bb[j]) =
                    *reinterpret_cast<const float4*>(&Bs[kk][tc * 8 + j]);
#pragma unroll
            for (int i = 0; i < 8; i++) {
#pragma unroll
                for (int j = 0; j < 8; j++) acc[i][j] += a[i] * bb[j];
            }
        }
        __syncthreads();
    }
#pragma unroll
    for (int i = 0; i < 8; i++) {
        int o = o0 + tr * 8 + i;
        float bv = bias[g * 256 + o];
        float* dst = pred + (size_t)(bg * 256 + o) * S_ + t0;
#pragma unroll
        for (int j = 0; j < 8; j++) {
            dst[tc * 8 + j] = acc[i][j] + bv;
        }
    }
}

// ---------------------------------------------------------------------------
extern "C" void kernel_launch(void* const* d_in, const int* in_sizes, int n_in,
                              void* d_out, int out_size) {
    const float* x      = (const float*)d_in[0];
    const float* w_qkv  = (const float*)d_in[1];
    const float* b_qkv  = (const float*)d_in[2];
    const float* w_pred = (const float*)d_in[3];
    const float* b_pred = (const float*)d_in[4];

    float* pred = (float*)d_out;
    float* attn = pred + (size_t)B_ * HID_ * S_;  // attn_out after pred

    qkv_gemm<<<dim3(33, 6, B_ * G_), 256>>>(x, w_qkv, b_qkv);
    attn_kernel<<<dim3(S_ / 128, NH_, B_), 128>>>(attn);
    pred_gemm<<<dim3(S_ / 128, 2, B_ * G_), 256>>>(w_pred, b_pred, pred);
}

// round 3
// speedup vs baseline: 1.8475x; 1.8475x over previous
#include <cuda_runtime.h>
#include <cuda_bf16.h>
#include <cstdint>

// ---------------------------------------------------------------------------
// Problem constants
constexpr int B_   = 4;
constexpr int G_   = 8;
constexpr int NH_  = 8;
constexpr int DIM_ = 256;    // HID / G
constexpr int S_   = 4096;
constexpr int SPAD = 4104;   // padded K/V time pitch (S_+1, rounded to 8)
constexpr int HID_ = 2048;
constexpr int KP   = 768;    // stacked K (3 x 256)

// ---------------------------------------------------------------------------
// Scratch (device globals; allocation is forbidden)
__device__ float g_Q[(size_t)B_ * G_ * DIM_ * S_];    // (bg, c, s)
__device__ float g_K[(size_t)B_ * G_ * DIM_ * SPAD];  // (bg, c, t) t in [0,4096]
__device__ float g_V[(size_t)B_ * G_ * DIM_ * SPAD];
__device__ float g_O[(size_t)B_ * G_ * DIM_ * S_];    // attention output

__device__ __nv_bfloat16 g_Bx[(size_t)32 * S_ * KP];  // x transposed+stacked [bg][t][k']
__device__ __nv_bfloat16 g_Bo[(size_t)32 * S_ * KP];  // O transposed+stacked
__device__ __nv_bfloat16 g_Aq[(size_t)G_ * 768 * KP]; // w_qkv stacked [g][o][k']
__device__ __nv_bfloat16 g_Ap[(size_t)G_ * 256 * KP]; // w_pred stacked

// ---------------------------------------------------------------------------
__device__ __forceinline__ uint32_t smem_u32(const void* p) {
    uint32_t a;
    asm("{ .reg .u64 t; cvta.to.shared.u64 t, %1; cvt.u32.u64 %0, t; }" : "=r"(a) : "l"(p));
    return a;
}
__device__ __forceinline__ void cp_async16(uint32_t dst, const void* src) {
    asm volatile("cp.async.cg.shared.global [%0], [%1], 16;" :: "r"(dst), "l"(src));
}
__device__ __forceinline__ void ldmatrix_x4(uint32_t* r, uint32_t addr) {
    asm volatile("ldmatrix.sync.aligned.m8n8.x4.shared.b16 {%0,%1,%2,%3}, [%4];"
                 : "=r"(r[0]), "=r"(r[1]), "=r"(r[2]), "=r"(r[3]) : "r"(addr));
}
__device__ __forceinline__ void mma16816(float* c, const uint32_t* a, uint32_t b0, uint32_t b1) {
    asm volatile(
        "mma.sync.aligned.m16n8k16.row.col.f32.bf16.bf16.f32 "
        "{%0,%1,%2,%3}, {%4,%5,%6,%7}, {%8,%9}, {%0,%1,%2,%3};"
        : "+f"(c[0]), "+f"(c[1]), "+f"(c[2]), "+f"(c[3])
        : "r"(a[0]), "r"(a[1]), "r"(a[2]), "r"(a[3]), "r"(b0), "r"(b1));
}

// ---------------------------------------------------------------------------
// Conversion: weights [R][256] fp32 -> [R][768] bf16 stacked [hi | lo | hi]
// ---------------------------------------------------------------------------
__global__ void convert_w(const float* __restrict__ w, __nv_bfloat16* __restrict__ A,
                          int total) {
    int i = blockIdx.x * 256 + threadIdx.x;
    if (i >= total) return;
    int r = i >> 8, c = i & 255;
    float v = w[i];
    __nv_bfloat16 h = __float2bfloat16(v);
    __nv_bfloat16 l = __float2bfloat16(v - __bfloat162float(h));
    __nv_bfloat16* row = A + (size_t)r * KP;
    row[c] = h;
    row[256 + c] = l;
    row[512 + c] = h;
}

// ---------------------------------------------------------------------------
// Transpose + convert: src [32 bg][256 c][4096 t] fp32 -> dst [bg][t][768] bf16
// stacked [hi | hi | lo]
// ---------------------------------------------------------------------------
__global__ __launch_bounds__(256)
void transpose_convert(const float* __restrict__ src, __nv_bfloat16* __restrict__ dst) {
    __shared__ float sm[32][33];
    int bg = blockIdx.z;
    int t0 = blockIdx.x * 32, c0 = blockIdx.y * 32;
    int tx = threadIdx.x, ty = threadIdx.y;  // 32 x 8
    const float* s = src + ((size_t)bg * 256 + c0) * S_ + t0;
#pragma unroll
    for (int i = 0; i < 4; i++)
        sm[ty * 4 + i][tx] = s[(size_t)(ty * 4 + i) * S_ + tx];
    __syncthreads();
    __nv_bfloat16* d0 = dst + ((size_t)bg * S_ + t0) * KP + c0;
#pragma unroll
    for (int i = 0; i < 4; i++) {
        int tl = ty * 4 + i;
        float v = sm[tx][tl];
        __nv_bfloat16 h = __float2bfloat16(v);
        __nv_bfloat16 l = __float2bfloat16(v - __bfloat162float(h));
        __nv_bfloat16* row = d0 + (size_t)tl * KP;
        row[tx] = h;
        row[256 + tx] = h;
        row[512 + tx] = l;
    }
}

// ---------------------------------------------------------------------------
// mma.sync GEMM: D[128 o x 128 t] = A[o][k'] . B[t][k'],  K' = 768
// 256 thr, 8 warps (4m x 2n), warp tile 32x64, BK=32, 3-stage cp.async.
// mode 0: QKV scatter (o -> c2, q/k/v) with bias; mode 1: pred write.
// ---------------------------------------------------------------------------
constexpr int NCH = KP / 32;  // 24 K-iterations

__global__ __launch_bounds__(256, 2)
void gemm_mma(const __nv_bfloat16* __restrict__ Aall,
              const __nv_bfloat16* __restrict__ Ball,
              const float* __restrict__ bias,
              int Mtot, int mode, float* __restrict__ out) {
    // per stage: A tile 128x32 bf16 (8KB, 64B rows) + B tile (8KB)
    __shared__ __align__(1024) char sbuf[3][16384];
    const int tid  = threadIdx.x;
    const int lane = tid & 31;
    const int wid  = tid >> 5;
    const int wm   = wid & 3;   // 0..3 (m slice of 32)
    const int wn   = wid >> 2;  // 0..1 (n slice of 64)
    const int bg = blockIdx.z, g = bg & 7;
    const int o0 = blockIdx.y * 128, t0 = blockIdx.x * 128;

    const uint32_t sbase = smem_u32(sbuf);
    const __nv_bfloat16* A  = Aall + ((size_t)g * Mtot + o0) * KP;
    const __nv_bfloat16* Bp = Ball + ((size_t)bg * S_ + t0) * KP;

    // cp.async layout: row pitch 64B, 4 x 16B chunks, swizzle c ^= (row>>1)&3
    auto load_stage = [&](int ch, int st) {
        uint32_t sA = sbase + st * 16384;
        uint32_t sB = sA + 8192;
        const char* a8 = (const char*)A  + (size_t)ch * 64;
        const char* b8 = (const char*)Bp + (size_t)ch * 64;
#pragma unroll
        for (int i = 0; i < 2; i++) {
            int id  = tid + i * 256;
            int row = id >> 2;
            int c   = id & 3;
            uint32_t off = row * 64 + ((c ^ ((row >> 1) & 3)) << 4);
            cp_async16(sA + off, a8 + (size_t)row * (KP * 2) + c * 16);
            cp_async16(sB + off, b8 + (size_t)row * (KP * 2) + c * 16);
        }
    };

    float acc[2][8][4];
#pragma unroll
    for (int mi = 0; mi < 2; mi++)
#pragma unroll
        for (int nj = 0; nj < 8; nj++)
#pragma unroll
            for (int q = 0; q < 4; q++) acc[mi][nj][q] = 0.f;

    load_stage(0, 0);
    asm volatile("cp.async.commit_group;" ::: "memory");
    load_stage(1, 1);
    asm volatile("cp.async.commit_group;" ::: "memory");

    const int gsel = lane >> 3;   // 0..3 (ldmatrix matrix select)
    const int rin  = lane & 7;

    for (int ch = 0; ch < NCH; ch++) {
        if (ch + 1 < NCH) asm volatile("cp.async.wait_group 1;" ::: "memory");
        else              asm volatile("cp.async.wait_group 0;" ::: "memory");
        __syncthreads();
        if (ch + 2 < NCH) {
            load_stage(ch + 2, (ch + 2) % 3);
            asm volatile("cp.async.commit_group;" ::: "memory");
        }
        uint32_t sA = sbase + (ch % 3) * 16384;
        uint32_t sB = sA + 8192;
#pragma unroll
        for (int kk = 0; kk < 2; kk++) {
            uint32_t afr[2][4];
#pragma unroll
            for (int mi = 0; mi < 2; mi++) {
                int row   = wm * 32 + mi * 16 + (gsel & 1) * 8 + rin;
                int chunk = kk * 2 + (gsel >> 1);
                uint32_t addr = sA + row * 64 + ((chunk ^ ((row >> 1) & 3)) << 4);
                ldmatrix_x4(afr[mi], addr);
            }
            uint32_t bfr[4][4];
#pragma unroll
            for (int nt = 0; nt < 4; nt++) {
                int row   = wn * 64 + nt * 16 + (gsel >> 1) * 8 + rin;
                int chunk = kk * 2 + (gsel & 1);
                uint32_t addr = sB + row * 64 + ((chunk ^ ((row >> 1) & 3)) << 4);
                ldmatrix_x4(bfr[nt], addr);
            }
#pragma unroll
            for (int mi = 0; mi < 2; mi++)
#pragma unroll
                for (int nj = 0; nj < 8; nj++)
                    mma16816(acc[mi][nj], afr[mi],
                             bfr[nj >> 1][(nj & 1) * 2], bfr[nj >> 1][(nj & 1) * 2 + 1]);
        }
        // buffer (ch+2)%3 overwritten next iter only after the next syncthreads
        __syncthreads();
    }

    // Epilogue: per-lane rows o, cols t
#pragma unroll
    for (int mi = 0; mi < 2; mi++) {
#pragma unroll
        for (int half = 0; half < 2; half++) {
            int o = o0 + wm * 32 + mi * 16 + half * 8 + (lane >> 2);
            float bv;
            float* dst;
            if (mode == 0) {
                int c2 = o / 3;
                int j  = o - c2 * 3;
                bv = bias[g * 768 + o];
                if (j == 0)      dst = g_Q + ((size_t)bg * DIM_ + c2) * S_;
                else if (j == 1) dst = g_K + ((size_t)bg * DIM_ + c2) * SPAD;
                else             dst = g_V + ((size_t)bg * DIM_ + c2) * SPAD;
            } else {
                bv  = bias[g * 256 + o];
                dst = out + ((size_t)bg * 256 + o) * S_;
            }
            dst += t0 + wn * 64 + (lane & 3) * 2;
#pragma unroll
            for (int nj = 0; nj < 8; nj++) {
                float2 v;
                v.x = acc[mi][nj][half * 2 + 0] + bv;
                v.y = acc[mi][nj][half * 2 + 1] + bv;
                *reinterpret_cast<float2*>(dst + nj * 8) = v;
            }
        }
    }
}

// ---------------------------------------------------------------------------
// Fill K/V pad column t=4096 with bias (x pad column is zero -> y = bias)
// ---------------------------------------------------------------------------
__global__ void fill_pad(const float* __restrict__ b_qkv) {
    int i = blockIdx.x * 256 + threadIdx.x;  // 32*256
    int bg = i >> 8, c2 = i & 255, g = bg & 7;
    g_K[((size_t)bg * DIM_ + c2) * SPAD + S_] = b_qkv[g * 768 + c2 * 3 + 1];
    g_V[((size_t)bg * DIM_ + c2) * SPAD + S_] = b_qkv[g * 768 + c2 * 3 + 2];
}

// ---------------------------------------------------------------------------
// Attention: one thread per (b, n, s); s = lane dim (coalesced).
// ---------------------------------------------------------------------------
__global__ __launch_bounds__(128)
void attn_kernel(float* __restrict__ attn_out) {
    const int s = blockIdx.x * 128 + threadIdx.x;
    const int n = blockIdx.y;
    const int b = blockIdx.z;

    float sc[8][16];
#pragma unroll
    for (int g = 0; g < 8; g++)
#pragma unroll
        for (int e = 0; e < 16; e++) sc[g][e] = 0.f;

    const size_t qbase = ((size_t)b * G_ * DIM_ + n * 32) * S_ + s;
    const size_t kbase = ((size_t)b * G_ * DIM_ + n * 32) * SPAD + s;

#pragma unroll 4
    for (int d = 0; d < 32; d++) {
        float qv[8], kv[16];
#pragma unroll
        for (int g = 0; g < 8; g++)
            qv[g] = g_Q[qbase + (size_t)(g * DIM_ + d) * S_];
#pragma unroll
        for (int e = 0; e < 8; e++) {
            size_t ko = kbase + (size_t)(e * DIM_ + d) * SPAD;
            kv[e]     = g_K[ko];
            kv[e + 8] = g_K[ko + 1];
        }
#pragma unroll
        for (int g = 0; g < 8; g++)
#pragma unroll
            for (int e = 0; e < 16; e++) sc[g][e] += qv[g] * kv[e];
    }

    const float scale = 0.17677669529663687f;  // 1/sqrt(32)
    const size_t abase = (size_t)(b * NH_ + n) * 128 * S_ + s;
#pragma unroll
    for (int g = 0; g < 8; g++) {
        float rs = 1e-9f;
#pragma unroll
        for (int e = 0; e < 16; e++) {
            float z = 1.f / (1.f + __expf(-sc[g][e] * scale));
            sc[g][e] = z;
            rs += z;
        }
        float inv = 1.f / rs;
#pragma unroll
        for (int e = 0; e < 16; e++) {
            sc[g][e] *= inv;
            attn_out[abase + (size_t)(g * 16 + e) * S_] = sc[g][e];
        }
    }

#pragma unroll 2
    for (int d = 0; d < 32; d++) {
        float vv[16];
#pragma unroll
        for (int e = 0; e < 8; e++) {
            size_t vo = kbase + (size_t)(e * DIM_ + d) * SPAD;
            vv[e]     = g_V[vo];
            vv[e + 8] = g_V[vo + 1];
        }
#pragma unroll
        for (int g = 0; g < 8; g++) {
            float a = 0.f;
#pragma unroll
            for (int e = 0; e < 16; e++) a += sc[g][e] * vv[e];
            g_O[qbase + (size_t)(g * DIM_ + d) * S_] = a;
        }
    }
}

// ---------------------------------------------------------------------------
extern "C" void kernel_launch(void* const* d_in, const int* in_sizes, int n_in,
                              void* d_out, int out_size) {
    const float* x      = (const float*)d_in[0];
    const float* w_qkv  = (const float*)d_in[1];
    const float* b_qkv  = (const float*)d_in[2];
    const float* w_pred = (const float*)d_in[3];
    const float* b_pred = (const float*)d_in[4];

    float* pred = (float*)d_out;
    float* attn = pred + (size_t)B_ * HID_ * S_;

    void *pAq, *pAp, *pBx, *pBo, *pO;
    cudaGetSymbolAddress(&pAq, g_Aq);
    cudaGetSymbolAddress(&pAp, g_Ap);
    cudaGetSymbolAddress(&pBx, g_Bx);
    cudaGetSymbolAddress(&pBo, g_Bo);
    cudaGetSymbolAddress(&pO,  g_O);

    convert_w<<<(G_ * 768 * 256 + 255) / 256, 256>>>(w_qkv, (__nv_bfloat16*)pAq, G_ * 768 * 256);
    convert_w<<<(G_ * 256 * 256 + 255) / 256, 256>>>(w_pred, (__nv_bfloat16*)pAp, G_ * 256 * 256);
    transpose_convert<<<dim3(128, 8, 32), dim3(32, 8)>>>(x, (__nv_bfloat16*)pBx);
    fill_pad<<<32, 256>>>(b_qkv);

    gemm_mma<<<dim3(32, 6, 32), 256>>>((const __nv_bfloat16*)pAq, (const __nv_bfloat16*)pBx,
                                       b_qkv, 768, 0, nullptr);

    attn_kernel<<<dim3(S_ / 128, NH_, B_), 128>>>(attn);

    transpose_convert<<<dim3(128, 8, 32), dim3(32, 8)>>>((const float*)pO, (__nv_bfloat16*)pBo);

    gemm_mma<<<dim3(32, 2, 32), 256>>>((const __nv_bfloat16*)pAp, (const __nv_bfloat16*)pBo,
                                       b_pred, 256, 1, pred);
}

// round 4
// speedup vs baseline: 2.2990x; 1.2444x over previous
#include <cuda_runtime.h>
#include <cuda_bf16.h>
#include <cstdint>

// ---------------------------------------------------------------------------
// Problem constants
constexpr int B_   = 4;
constexpr int G_   = 8;
constexpr int NH_  = 8;
constexpr int DIM_ = 256;    // HID / G
constexpr int S_   = 4096;
constexpr int SPAD = 4104;   // padded K/V time pitch (S_+1, rounded to 8)
constexpr int HID_ = 2048;
constexpr int KP   = 768;    // stacked K for A operand (3 x 256: hi|lo|hi)

// ---------------------------------------------------------------------------
// Scratch (device globals; allocation is forbidden)
__device__ float g_Q[(size_t)B_ * G_ * DIM_ * S_];    // (bg, c, s)
__device__ float g_K[(size_t)B_ * G_ * DIM_ * SPAD];  // (bg, c, t) t in [0,4096]
__device__ float g_V[(size_t)B_ * G_ * DIM_ * SPAD];

// B operands in [bg][512 rows][4096 t]:  rows 0-255 = hi(c), rows 256-511 = lo(c)
__device__ __nv_bfloat16 g_Bx[(size_t)32 * 512 * S_];
__device__ __nv_bfloat16 g_Bo[(size_t)32 * 512 * S_];
__device__ __nv_bfloat16 g_Aq[(size_t)G_ * 768 * KP]; // w_qkv stacked [g][o][hi|lo|hi]
__device__ __nv_bfloat16 g_Ap[(size_t)G_ * 256 * KP]; // w_pred stacked

// ---------------------------------------------------------------------------
__device__ __forceinline__ uint32_t smem_u32(const void* p) {
    uint32_t a;
    asm("{ .reg .u64 t; cvta.to.shared.u64 t, %1; cvt.u32.u64 %0, t; }" : "=r"(a) : "l"(p));
    return a;
}
__device__ __forceinline__ void cp_async16(uint32_t dst, const void* src) {
    asm volatile("cp.async.cg.shared.global [%0], [%1], 16;" :: "r"(dst), "l"(src));
}
__device__ __forceinline__ void ldmatrix_x4(uint32_t* r, uint32_t addr) {
    asm volatile("ldmatrix.sync.aligned.m8n8.x4.shared.b16 {%0,%1,%2,%3}, [%4];"
                 : "=r"(r[0]), "=r"(r[1]), "=r"(r[2]), "=r"(r[3]) : "r"(addr));
}
__device__ __forceinline__ void ldmatrix_x4_trans(uint32_t* r, uint32_t addr) {
    asm volatile("ldmatrix.sync.aligned.m8n8.x4.trans.shared.b16 {%0,%1,%2,%3}, [%4];"
                 : "=r"(r[0]), "=r"(r[1]), "=r"(r[2]), "=r"(r[3]) : "r"(addr));
}
__device__ __forceinline__ void mma16816(float* c, const uint32_t* a, uint32_t b0, uint32_t b1) {
    asm volatile(
        "mma.sync.aligned.m16n8k16.row.col.f32.bf16.bf16.f32 "
        "{%0,%1,%2,%3}, {%4,%5,%6,%7}, {%8,%9}, {%0,%1,%2,%3};"
        : "+f"(c[0]), "+f"(c[1]), "+f"(c[2]), "+f"(c[3])
        : "r"(a[0]), "r"(a[1]), "r"(a[2]), "r"(a[3]), "r"(b0), "r"(b1));
}

// ---------------------------------------------------------------------------
// Weights [R][256] fp32 -> [R][768] bf16 stacked [hi | lo | hi]
// ---------------------------------------------------------------------------
__global__ void convert_w(const float* __restrict__ w, __nv_bfloat16* __restrict__ A,
                          int total) {
    int i = blockIdx.x * 256 + threadIdx.x;
    if (i >= total) return;
    int r = i >> 8, c = i & 255;
    float v = w[i];
    __nv_bfloat16 h = __float2bfloat16(v);
    __nv_bfloat16 l = __float2bfloat16(v - __bfloat162float(h));
    __nv_bfloat16* row = A + (size_t)r * KP;
    row[c] = h;
    row[256 + c] = l;
    row[512 + c] = h;
}

// ---------------------------------------------------------------------------
// x [bg][256 c][4096 t] fp32 -> g_Bx [bg][512][4096] bf16 (row c = hi, 256+c = lo)
// Pure elementwise, fully coalesced; no transpose.
// ---------------------------------------------------------------------------
__global__ __launch_bounds__(256)
void convert_x(const float* __restrict__ x, __nv_bfloat16* __restrict__ dst) {
    int i = blockIdx.x * 256 + threadIdx.x;  // over 32*256*1024 float4 slots
    int t4 = (i & 1023) << 2;
    int c  = (i >> 10) & 255;
    int bg = i >> 18;
    float4 v = *reinterpret_cast<const float4*>(x + ((size_t)bg * 256 + c) * S_ + t4);
    __nv_bfloat162 h0, h1, l0, l1;
    h0.x = __float2bfloat16(v.x); h0.y = __float2bfloat16(v.y);
    h1.x = __float2bfloat16(v.z); h1.y = __float2bfloat16(v.w);
    l0.x = __float2bfloat16(v.x - __bfloat162float(h0.x));
    l0.y = __float2bfloat16(v.y - __bfloat162float(h0.y));
    l1.x = __float2bfloat16(v.z - __bfloat162float(h1.x));
    l1.y = __float2bfloat16(v.w - __bfloat162float(h1.y));
    __nv_bfloat162* dh = reinterpret_cast<__nv_bfloat162*>(
        dst + ((size_t)bg * 512 + c) * S_ + t4);
    dh[0] = h0; dh[1] = h1;
    __nv_bfloat162* dl = reinterpret_cast<__nv_bfloat162*>(
        dst + ((size_t)bg * 512 + 256 + c) * S_ + t4);
    dl[0] = l0; dl[1] = l1;
}

// ---------------------------------------------------------------------------
// mma.sync GEMM: D[128 o x 128 t] = A[o][k'stacked768] . B[t][k 512]
// A K-major (non-trans ldmatrix), B [k][t] via ldmatrix.trans.
// ch 0-7:  A hi  x B hi ; ch 8-15: A lo x B hi ; ch 16-23: A hi x B lo
// ---------------------------------------------------------------------------
constexpr int NCH = 24;

__global__ __launch_bounds__(256, 2)
void gemm_mma(const __nv_bfloat16* __restrict__ Aall,
              const __nv_bfloat16* __restrict__ Ball,
              const float* __restrict__ bias,
              int Mtot, int mode, float* __restrict__ out) {
    // per stage: A tile 128(o)x32(k) bf16 8KB (64B rows) + B tile 32(k)x128(t) 8KB (256B rows)
    __shared__ __align__(1024) char sbuf[3][16384];
    const int tid  = threadIdx.x;
    const int lane = tid & 31;
    const int wid  = tid >> 5;
    const int wm   = wid & 3;   // m slice of 32
    const int wn   = wid >> 2;  // n slice of 64
    const int bg = blockIdx.z, g = bg & 7;
    const int o0 = blockIdx.y * 128, t0 = blockIdx.x * 128;

    const uint32_t sbase = smem_u32(sbuf);
    const __nv_bfloat16* A  = Aall + ((size_t)g * Mtot + o0) * KP;
    const __nv_bfloat16* Bp = Ball + (size_t)bg * 512 * S_;

    auto load_stage = [&](int ch, int st) {
        uint32_t sA = sbase + st * 16384;
        uint32_t sB = sA + 8192;
        const char* a8 = (const char*)A + (size_t)ch * 64;
        int bch = (ch < 8) ? ch : ch - 8;  // B k-chunk (rows bch*32 ..)
        const char* b8 = (const char*)(Bp + ((size_t)bch * 32) * S_ + t0);
#pragma unroll
        for (int i = 0; i < 2; i++) {
            int id  = tid + i * 256;
            // A: 128 rows x 4 chunks
            int ra = id >> 2, ca = id & 3;
            uint32_t offA = ra * 64 + ((ca ^ ((ra >> 1) & 3)) << 4);
            cp_async16(sA + offA, a8 + (size_t)ra * (KP * 2) + ca * 16);
            // B: 32 rows x 16 chunks
            int rb = id >> 4, cb = id & 15;
            uint32_t offB = rb * 256 + ((cb ^ (rb & 7)) << 4);
            cp_async16(sB + offB, b8 + (size_t)rb * (S_ * 2) + cb * 16);
        }
    };

    float acc[2][8][4];
#pragma unroll
    for (int mi = 0; mi < 2; mi++)
#pragma unroll
        for (int nj = 0; nj < 8; nj++)
#pragma unroll
            for (int q = 0; q < 4; q++) acc[mi][nj][q] = 0.f;

    load_stage(0, 0);
    asm volatile("cp.async.commit_group;" ::: "memory");
    load_stage(1, 1);
    asm volatile("cp.async.commit_group;" ::: "memory");

    const int gsel = lane >> 3;   // A ldmatrix select
    const int rin  = lane & 7;
    const int bl   = lane & 15;   // B trans-ldmatrix row-in-16
    const int bh   = lane >> 4;   // B n8-half select

    for (int ch = 0; ch < NCH; ch++) {
        if (ch + 1 < NCH) asm volatile("cp.async.wait_group 1;" ::: "memory");
        else              asm volatile("cp.async.wait_group 0;" ::: "memory");
        __syncthreads();
        if (ch + 2 < NCH) {
            load_stage(ch + 2, (ch + 2) % 3);
            asm volatile("cp.async.commit_group;" ::: "memory");
        }
        uint32_t sA = sbase + (ch % 3) * 16384;
        uint32_t sB = sA + 8192;
#pragma unroll
        for (int kk = 0; kk < 2; kk++) {
            uint32_t afr[2][4];
#pragma unroll
            for (int mi = 0; mi < 2; mi++) {
                int row   = wm * 32 + mi * 16 + (gsel & 1) * 8 + rin;
                int chunk = kk * 2 + (gsel >> 1);
                uint32_t addr = sA + row * 64 + ((chunk ^ ((row >> 1) & 3)) << 4);
                ldmatrix_x4(afr[mi], addr);
            }
            uint32_t bfr[4][4];
#pragma unroll
            for (int nt = 0; nt < 4; nt++) {
                int krow  = kk * 16 + bl;                   // k row in tile
                int chunk = wn * 8 + nt * 2 + bh;           // 16B chunk along t
                uint32_t addr = sB + krow * 256 + ((chunk ^ (krow & 7)) << 4);
                ldmatrix_x4_trans(bfr[nt], addr);           // {b0_n0,b1_n0,b0_n8,b1_n8}
            }
#pragma unroll
            for (int mi = 0; mi < 2; mi++)
#pragma unroll
                for (int nj = 0; nj < 8; nj++)
                    mma16816(acc[mi][nj], afr[mi],
                             bfr[nj >> 1][(nj & 1) * 2], bfr[nj >> 1][(nj & 1) * 2 + 1]);
        }
        __syncthreads();
    }

    // Epilogue
#pragma unroll
    for (int mi = 0; mi < 2; mi++) {
#pragma unroll
        for (int half = 0; half < 2; half++) {
            int o = o0 + wm * 32 + mi * 16 + half * 8 + (lane >> 2);
            float bv;
            float* dst;
            if (mode == 0) {
                int c2 = o / 3;
                int j  = o - c2 * 3;
                bv = bias[g * 768 + o];
                if (j == 0)      dst = g_Q + ((size_t)bg * DIM_ + c2) * S_;
                else if (j == 1) dst = g_K + ((size_t)bg * DIM_ + c2) * SPAD;
                else             dst = g_V + ((size_t)bg * DIM_ + c2) * SPAD;
            } else {
                bv  = bias[g * 256 + o];
                dst = out + ((size_t)bg * 256 + o) * S_;
            }
            dst += t0 + wn * 64 + (lane & 3) * 2;
#pragma unroll
            for (int nj = 0; nj < 8; nj++) {
                float2 v;
                v.x = acc[mi][nj][half * 2 + 0] + bv;
                v.y = acc[mi][nj][half * 2 + 1] + bv;
                *reinterpret_cast<float2*>(dst + nj * 8) = v;
            }
        }
    }
}

// ---------------------------------------------------------------------------
// Fill K/V pad column t=4096 with bias
// ---------------------------------------------------------------------------
__global__ void fill_pad(const float* __restrict__ b_qkv) {
    int i = blockIdx.x * 256 + threadIdx.x;  // 32*256
    int bg = i >> 8, c2 = i & 255, g = bg & 7;
    g_K[((size_t)bg * DIM_ + c2) * SPAD + S_] = b_qkv[g * 768 + c2 * 3 + 1];
    g_V[((size_t)bg * DIM_ + c2) * SPAD + S_] = b_qkv[g * 768 + c2 * 3 + 2];
}

// ---------------------------------------------------------------------------
// Attention: one thread per (b, n, s). Writes attn_out fp32 and the attention
// output DIRECTLY as hi/lo bf16 into g_Bo (pred GEMM's B operand).
// ---------------------------------------------------------------------------
__global__ __launch_bounds__(128)
void attn_kernel(float* __restrict__ attn_out) {
    const int s = blockIdx.x * 128 + threadIdx.x;
    const int n = blockIdx.y;
    const int b = blockIdx.z;

    float sc[8][16];
#pragma unroll
    for (int g = 0; g < 8; g++)
#pragma unroll
        for (int e = 0; e < 16; e++) sc[g][e] = 0.f;

    const size_t qbase = ((size_t)b * G_ * DIM_ + n * 32) * S_ + s;
    const size_t kbase = ((size_t)b * G_ * DIM_ + n * 32) * SPAD + s;

#pragma unroll 4
    for (int d = 0; d < 32; d++) {
        float qv[8], kv[16];
#pragma unroll
        for (int g = 0; g < 8; g++)
            qv[g] = g_Q[qbase + (size_t)(g * DIM_ + d) * S_];
#pragma unroll
        for (int e = 0; e < 8; e++) {
            size_t ko = kbase + (size_t)(e * DIM_ + d) * SPAD;
            kv[e]     = g_K[ko];
            kv[e + 8] = g_K[ko + 1];
        }
#pragma unroll
        for (int g = 0; g < 8; g++)
#pragma unroll
            for (int e = 0; e < 16; e++) sc[g][e] += qv[g] * kv[e];
    }

    const float scale = 0.17677669529663687f;  // 1/sqrt(32)
    const size_t abase = (size_t)(b * NH_ + n) * 128 * S_ + s;
#pragma unroll
    for (int g = 0; g < 8; g++) {
        float rs = 1e-9f;
#pragma unroll
        for (int e = 0; e < 16; e++) {
            float z = 1.f / (1.f + __expf(-sc[g][e] * scale));
            sc[g][e] = z;
            rs += z;
        }
        float inv = 1.f / rs;
#pragma unroll
        for (int e = 0; e < 16; e++) {
            sc[g][e] *= inv;
            attn_out[abase + (size_t)(g * 16 + e) * S_] = sc[g][e];
        }
    }

    // AV + direct hi/lo write into g_Bo[bg][c]=hi, [bg][256+c]=lo, c = n*32+d
#pragma unroll 2
    for (int d = 0; d < 32; d++) {
        float vv[16];
#pragma unroll
        for (int e = 0; e < 8; e++) {
            size_t vo = kbase + (size_t)(e * DIM_ + d) * SPAD;
            vv[e]     = g_V[vo];
            vv[e + 8] = g_V[vo + 1];
        }
#pragma unroll
        for (int g = 0; g < 8; g++) {
            float a = 0.f;
#pragma unroll
            for (int e = 0; e < 16; e++) a += sc[g][e] * vv[e];
            __nv_bfloat16 h = __float2bfloat16(a);
            __nv_bfloat16 l = __float2bfloat16(a - __bfloat162float(h));
            size_t base = ((size_t)(b * 8 + g) * 512 + n * 32 + d) * S_ + s;
            g_Bo[base]            = h;
            g_Bo[base + 256 * S_] = l;
        }
    }
}

// ---------------------------------------------------------------------------
extern "C" void kernel_launch(void* const* d_in, const int* in_sizes, int n_in,
                              void* d_out, int out_size) {
    const float* x      = (const float*)d_in[0];
    const float* w_qkv  = (const float*)d_in[1];
    const float* b_qkv  = (const float*)d_in[2];
    const float* w_pred = (const float*)d_in[3];
    const float* b_pred = (const float*)d_in[4];

    float* pred = (float*)d_out;
    float* attn = pred + (size_t)B_ * HID_ * S_;

    void *pAq, *pAp, *pBx, *pBo;
    cudaGetSymbolAddress(&pAq, g_Aq);
    cudaGetSymbolAddress(&pAp, g_Ap);
    cudaGetSymbolAddress(&pBx, g_Bx);
    cudaGetSymbolAddress(&pBo, g_Bo);

    convert_w<<<(G_ * 768 * 256 + 255) / 256, 256>>>(w_qkv, (__nv_bfloat16*)pAq, G_ * 768 * 256);
    convert_w<<<(G_ * 256 * 256 + 255) / 256, 256>>>(w_pred, (__nv_bfloat16*)pAp, G_ * 256 * 256);
    convert_x<<<32 * 256 * 1024 / 256, 256>>>(x, (__nv_bfloat16*)pBx);
    fill_pad<<<32, 256>>>(b_qkv);

    gemm_mma<<<dim3(32, 6, 32), 256>>>((const __nv_bfloat16*)pAq, (const __nv_bfloat16*)pBx,
                                       b_qkv, 768, 0, nullptr);

    attn_kernel<<<dim3(S_ / 128, NH_, B_), 128>>>(attn);

    gemm_mma<<<dim3(32, 2, 32), 256>>>((const __nv_bfloat16*)pAp, (const __nv_bfloat16*)pBo,
                                       b_pred, 256, 1, pred);
}